// round 1
// baseline (speedup 1.0000x reference)
#include <cuda_runtime.h>
#include <cstdint>

#define LL      8192
#define BATCH   32
#define NF      128
#define NT      128
#define KSPLIT  8
#define KCH     (LL / KSPLIT)

// Precomputed tables, K-major for coalesced GEMM loads.
__device__ float g_CT[LL * NF];  // [l][f]  cos modulation
__device__ float g_WT[LL * NT];  // [l][t]  gaussian window

// ---------------------------------------------------------------------------
// Table precompute. Replicates the reference's fp32 phase rounding exactly:
//   theta_ref = fl( fl( fl(2pi_f32 * f) * l ) / 8192 )
// Decompose: theta = 2*pi*m/8192 + eps, m = (f*l) mod 8192 exact,
//   eps = (D*f*l - e1*l - e2)/8192, with twoProd residuals e1, e2 and
//   D = 2pi_f32 - 2pi_exact. Then cos(theta) ~= cospi(x) - eps*sinpi(x).
// ---------------------------------------------------------------------------
__global__ void prep_tables() {
    int idx = blockIdx.x * blockDim.x + threadIdx.x;
    const int totC = LL * NF;
    if (idx < totC) {
        int f = idx & (NF - 1);
        int l = idx >> 7;
        int fi = (f * 4096) / 127;             // exact linspace->int truncation
        float fv = (float)fi;
        float lf = (float)l;
        const float TP = 6.2831854820251465f;  // fl(2*pi)
        const float DD = 1.7484556e-7f;        // fl(2*pi) - 2*pi (exact defect)
        float a  = TP * fv;
        float e1 = fmaf(TP, fv, -a);           // TP*fv - a, exact
        float bb = a * lf;
        float e2 = fmaf(a, lf, -bb);           // a*lf - bb, exact
        // theta = 2pi*(fi*l)/8192 + eps
        float eps = (DD * (fv * lf) - e1 * lf - e2) * (1.0f / 8192.0f);
        int m = (fi * l) & (LL - 1);
        float x = (float)m * (1.0f / 4096.0f); // phase / pi
        float s, c;
        sincospif(x, &s, &c);
        g_CT[idx] = c - eps * s;
    } else {
        int j = idx - totC;
        if (j < LL * NT) {
            int t = j & (NT - 1);
            int l = j >> 7;
            int tci = (t * 8191) / 127;        // exact linspace->int truncation
            float diff = (float)l - (float)tci;
            float x = diff / 819.2f;           // sigma_w in f32, same as ref
            g_WT[j] = expf(-0.5f * (x * x));
        }
    }
}

__global__ void zero_out(float* out, int n) {
    int i = blockIdx.x * blockDim.x + threadIdx.x;
    if (i < n) out[i] = 0.0f;
}

// ---------------------------------------------------------------------------
// Batched GEMM: out[b][f][t] += sum_{l in K-chunk} CT[l][f] * (sig[b][l]*WT[l][t])
// grid = (4 tiles, KSPLIT, BATCH); block = 256 threads; 64x64 tile, 4x4/thread.
// ---------------------------------------------------------------------------
__global__ void __launch_bounds__(256)
gabor_gemm(const float* __restrict__ sig, float* __restrict__ out) {
    const int ft0 = (blockIdx.x >> 1) * 64;
    const int tt0 = (blockIdx.x & 1) * 64;
    const int k0  = blockIdx.y * KCH;
    const int b   = blockIdx.z;

    __shared__ float Cs[64][68];   // [l][f], padded to avoid bank conflicts
    __shared__ float Xs[64][68];   // [l][t]

    const int tid = threadIdx.x;
    const int ty = tid >> 4;       // 0..15 -> f sub-tile
    const int tx = tid & 15;       // 0..15 -> t sub-tile

    float acc[4][4];
#pragma unroll
    for (int i = 0; i < 4; i++)
#pragma unroll
        for (int j = 0; j < 4; j++) acc[i][j] = 0.0f;

    const float* sigb = sig + b * LL;

    for (int kc = 0; kc < KCH; kc += 64) {
        __syncthreads();
#pragma unroll
        for (int p = 0; p < 4; p++) {
            int r = ty + 16 * p;
            int gl = k0 + kc + r;
            float4 cv = *(const float4*)&g_CT[gl * NF + ft0 + tx * 4];
            float4 wv = *(const float4*)&g_WT[gl * NT + tt0 + tx * 4];
            float sv = sigb[gl];
            wv.x *= sv; wv.y *= sv; wv.z *= sv; wv.w *= sv;
            *(float4*)&Cs[r][tx * 4] = cv;
            *(float4*)&Xs[r][tx * 4] = wv;
        }
        __syncthreads();

#pragma unroll 8
        for (int kk = 0; kk < 64; kk++) {
            float4 cf = *(const float4*)&Cs[kk][ty * 4];
            float4 xf = *(const float4*)&Xs[kk][tx * 4];
            float cr[4] = {cf.x, cf.y, cf.z, cf.w};
            float xr[4] = {xf.x, xf.y, xf.z, xf.w};
#pragma unroll
            for (int i = 0; i < 4; i++)
#pragma unroll
                for (int j = 0; j < 4; j++)
                    acc[i][j] = fmaf(cr[i], xr[j], acc[i][j]);
        }
    }

    float* outb = out + b * (NF * NT);
#pragma unroll
    for (int i = 0; i < 4; i++) {
        int f = ft0 + ty * 4 + i;
#pragma unroll
        for (int j = 0; j < 4; j++) {
            int t = tt0 + tx * 4 + j;
            atomicAdd(&outb[f * NT + t], acc[i][j]);
        }
    }
}

extern "C" void kernel_launch(void* const* d_in, const int* in_sizes, int n_in,
                              void* d_out, int out_size) {
    const float* sig = (const float*)d_in[0];
    float* out = (float*)d_out;

    int prep_threads = 2 * LL * 128;
    prep_tables<<<(prep_threads + 255) / 256, 256>>>();
    zero_out<<<(out_size + 255) / 256, 256>>>(out, out_size);

    dim3 grid(4, KSPLIT, BATCH);
    gabor_gemm<<<grid, 256>>>(sig, out);
}

// round 4
// speedup vs baseline: 1.6898x; 1.6898x over previous
#include <cuda_runtime.h>
#include <cuda_bf16.h>
#include <cstdint>

#define LL      8192
#define BATCH   32
#define NF      128
#define NT      128
#define KS      4
#define KR      (LL/KS)       // 2048
#define NSTG    (KR/64)       // 32 stages of k64

// ---- global tables / scratch ----
__device__ __align__(16) __nv_bfloat16 g_Chi[LL*NF];  // tiled [l/64][f][64k]
__device__ __align__(16) __nv_bfloat16 g_Clo[LL*NF];
__device__ __align__(16) float         g_W[NT*LL];    // [t][l]
__device__ __align__(16) float         g_part[KS*BATCH*NF*NT];  // 8MB

// ---- smem layout (bytes). Rows padded to 144B (72 bf16) => conflict-free ldsm ----
#define TILEB   18432                      // 128 rows * 144B
#define OFF_AH(buf) ((buf)*2*TILEB)
#define OFF_AL(buf) ((buf)*2*TILEB + TILEB)
#define OFF_BH(buf) (4*TILEB + (buf)*2*TILEB)
#define OFF_BL(buf) (4*TILEB + (buf)*2*TILEB + TILEB)
#define OFF_SIG (8*TILEB)                  // 147456
#define SMEM_DYN (OFF_SIG + KR*4)          // 155648

// ---- PTX helpers ----
__device__ __forceinline__ uint32_t smem_u32(const void* p) {
    uint32_t a;
    asm("{ .reg .u64 t; cvta.to.shared.u64 t, %1; cvt.u32.u64 %0, t; }" : "=r"(a) : "l"(p));
    return a;
}
__device__ __forceinline__ void cpa16(uint32_t dst, const void* src) {
    asm volatile("cp.async.ca.shared.global [%0], [%1], 16;" :: "r"(dst), "l"(src));
}
#define CP_COMMIT() asm volatile("cp.async.commit_group;" ::: "memory")
#define CP_WAIT0()  asm volatile("cp.async.wait_group 0;" ::: "memory")

__device__ __forceinline__ void ldsm4(uint32_t r[4], uint32_t addr) {
    asm volatile("ldmatrix.sync.aligned.m8n8.x4.shared.b16 {%0,%1,%2,%3}, [%4];"
                 : "=r"(r[0]), "=r"(r[1]), "=r"(r[2]), "=r"(r[3]) : "r"(addr));
}
__device__ __forceinline__ void mma16816(float c[4], const uint32_t a[4],
                                         uint32_t b0, uint32_t b1) {
    asm volatile("mma.sync.aligned.m16n8k16.row.col.f32.bf16.bf16.f32 "
                 "{%0,%1,%2,%3}, {%4,%5,%6,%7}, {%8,%9}, {%0,%1,%2,%3};"
                 : "+f"(c[0]), "+f"(c[1]), "+f"(c[2]), "+f"(c[3])
                 : "r"(a[0]), "r"(a[1]), "r"(a[2]), "r"(a[3]), "r"(b0), "r"(b1));
}
// pack two fp32 -> bf16x2 (first arg -> low half = lower k index)
__device__ __forceinline__ uint32_t cvt2(float lo, float hi) {
    uint32_t r;
    asm("cvt.rn.bf16x2.f32 %0, %1, %2;" : "=r"(r) : "f"(hi), "f"(lo));
    return r;
}

// ---------------------------------------------------------------------------
// Tables. Exact fp32-phase replication (R1: rel_err 8e-7), bf16 hi/lo split.
// g_Chi/g_Clo layout: contiguous 16KB tiles [l/64][f][64], no swizzle.
// ---------------------------------------------------------------------------
__global__ void prep_tables() {
    int idx = blockIdx.x * blockDim.x + threadIdx.x;
    const int totC = LL * NF;
    if (idx < totC) {
        int tile = idx >> 13;
        int r    = idx & 8191;
        int f    = r >> 6;
        int c    = r & 63;
        int l    = tile * 64 + c;
        int fi = (f * 4096) / 127;
        float fv = (float)fi, lf = (float)l;
        const float TP = 6.2831854820251465f;
        const float DD = 1.7484556e-7f;
        float a  = TP * fv;
        float e1 = fmaf(TP, fv, -a);
        float bb = a * lf;
        float e2 = fmaf(a, lf, -bb);
        float eps = (DD * (fv * lf) - e1 * lf - e2) * (1.0f / 8192.0f);
        int m = (fi * l) & (LL - 1);
        float x = (float)m * (1.0f / 4096.0f);
        float s, cc;
        sincospif(x, &s, &cc);
        float cosv = cc - eps * s;
        __nv_bfloat16 hi = __float2bfloat16(cosv);
        float hif = __bfloat162float(hi);
        g_Chi[idx] = hi;
        g_Clo[idx] = __float2bfloat16(cosv - hif);
    } else if (idx < 2 * totC) {
        int j = idx - totC;
        int t = j >> 13;
        int l = j & 8191;
        int tci = (t * 8191) / 127;
        float diff = (float)l - (float)tci;
        float x = diff / 819.2f;
        g_W[j] = expf(-0.5f * (x * x));
    }
}

// ---------------------------------------------------------------------------
// Main GEMM: out_part[ks][b][f][t] = sum_{k in range} C[f,k] * (sig[b,k]*W[t,k])
// 3-term bf16 split via mma.sync m16n8k16. grid=(KS, BATCH), 256 threads.
// B stored [t][k] (k contiguous) == col-major kxn -> NON-trans ldmatrix.
// ---------------------------------------------------------------------------
__global__ void __launch_bounds__(256, 1)
gabor_mma(const float* __restrict__ sig) {
    extern __shared__ __align__(16) char smc[];
    const uint32_t smb = smem_u32(smc);
    const int tid = threadIdx.x, lane = tid & 31, wid = tid >> 5;
    const int ks = blockIdx.x, b = blockIdx.y;
    const int kbase = ks * KR;

    // signal chunk -> smem
    float* ssm = (float*)(smc + OFF_SIG);
    {
        const float4* sp = (const float4*)(sig + b * LL + kbase);
        float4* dp = (float4*)ssm;
        for (int i = tid; i < KR / 4; i += 256) dp[i] = sp[i];
    }
    __syncthreads();

    auto copyA = [&](int s, int buf) {
        const int gt = ks * NSTG + s;
        const char* srch = (const char*)g_Chi + (size_t)gt * 16384;
        const char* srcl = (const char*)g_Clo + (size_t)gt * 16384;
        const uint32_t dh = smb + OFF_AH(buf), dl = smb + OFF_AL(buf);
#pragma unroll
        for (int r = 0; r < 4; r++) {
            int j = tid + 256 * r;               // 0..1023 16B chunks
            uint32_t doff = (uint32_t)(j >> 3) * 144 + (j & 7) * 16;
            cpa16(dh + doff, srch + j * 16);
            cpa16(dl + doff, srcl + j * 16);
        }
    };

    const int tp = tid >> 1, hh = tid & 1;
    auto buildP = [&](int s, int buf) {
        const float* wrow = g_W + tp * LL + kbase + s * 64 + 32 * hh;
        const float* sp   = ssm + s * 64 + 32 * hh;
        char* ph = smc + OFF_BH(buf) + tp * 144 + 64 * hh;
        char* pl = smc + OFF_BL(buf) + tp * 144 + 64 * hh;
#pragma unroll
        for (int m = 0; m < 4; m++) {
            float4 wa = ((const float4*)wrow)[2 * m];
            float4 wb = ((const float4*)wrow)[2 * m + 1];
            float4 sa = ((const float4*)sp)[2 * m];
            float4 sb = ((const float4*)sp)[2 * m + 1];
            float p0 = sa.x * wa.x, p1 = sa.y * wa.y, p2 = sa.z * wa.z, p3 = sa.w * wa.w;
            float p4 = sb.x * wb.x, p5 = sb.y * wb.y, p6 = sb.z * wb.z, p7 = sb.w * wb.w;
            uint32_t h0 = cvt2(p0, p1), h1 = cvt2(p2, p3);
            uint32_t h2 = cvt2(p4, p5), h3 = cvt2(p6, p7);
            uint32_t l0 = cvt2(p0 - __uint_as_float(h0 << 16), p1 - __uint_as_float(h0 & 0xffff0000u));
            uint32_t l1 = cvt2(p2 - __uint_as_float(h1 << 16), p3 - __uint_as_float(h1 & 0xffff0000u));
            uint32_t l2 = cvt2(p4 - __uint_as_float(h2 << 16), p5 - __uint_as_float(h2 & 0xffff0000u));
            uint32_t l3 = cvt2(p6 - __uint_as_float(h3 << 16), p7 - __uint_as_float(h3 & 0xffff0000u));
            *(uint4*)(ph + 16 * m) = make_uint4(h0, h1, h2, h3);
            *(uint4*)(pl + 16 * m) = make_uint4(l0, l1, l2, l3);
        }
    };

    // prologue
    copyA(0, 0); CP_COMMIT();
    buildP(0, 0);

    float acc[2][8][4];
#pragma unroll
    for (int m = 0; m < 2; m++)
#pragma unroll
        for (int n = 0; n < 8; n++)
#pragma unroll
            for (int q = 0; q < 4; q++) acc[m][n][q] = 0.0f;

    const int f0 = (wid & 3) * 32, t0 = (wid >> 2) * 64;
    const uint32_t loff = (uint32_t)(lane & 15) * 144 + (lane >> 4) * 16;

    for (int s = 0; s < NSTG; s++) {
        CP_WAIT0();
        __syncthreads();
        const int buf = s & 1;
        if (s + 1 < NSTG) {
            copyA(s + 1, buf ^ 1); CP_COMMIT();
            buildP(s + 1, buf ^ 1);
        }
        const uint32_t aH = smb + OFF_AH(buf) + f0 * 144 + loff;
        const uint32_t aL = smb + OFF_AL(buf) + f0 * 144 + loff;
        const uint32_t bH = smb + OFF_BH(buf) + t0 * 144 + loff;
        const uint32_t bL = smb + OFF_BL(buf) + t0 * 144 + loff;
#pragma unroll
        for (int k16 = 0; k16 < 4; k16++) {
            const uint32_t kb = k16 * 32;
            uint32_t ah[2][4], al[2][4], bh[4][4], bl[4][4];
            ldsm4(ah[0], aH + kb); ldsm4(ah[1], aH + 16 * 144 + kb);
            ldsm4(al[0], aL + kb); ldsm4(al[1], aL + 16 * 144 + kb);
#pragma unroll
            for (int j = 0; j < 4; j++) {
                ldsm4(bh[j], bH + j * 16 * 144 + kb);
                ldsm4(bl[j], bL + j * 16 * 144 + kb);
            }
#pragma unroll
            for (int m = 0; m < 2; m++)
#pragma unroll
                for (int j = 0; j < 4; j++) {
                    mma16816(acc[m][2 * j],     ah[m], bh[j][0], bh[j][2]);
                    mma16816(acc[m][2 * j + 1], ah[m], bh[j][1], bh[j][3]);
                    mma16816(acc[m][2 * j],     al[m], bh[j][0], bh[j][2]);
                    mma16816(acc[m][2 * j + 1], al[m], bh[j][1], bh[j][3]);
                    mma16816(acc[m][2 * j],     ah[m], bl[j][0], bl[j][2]);
                    mma16816(acc[m][2 * j + 1], ah[m], bl[j][1], bl[j][3]);
                }
        }
    }

    // epilogue: write partials
    float* dst = g_part + (size_t)(ks * BATCH + b) * NF * NT;
    const int r0 = lane >> 2, c0 = (lane & 3) * 2;
#pragma unroll
    for (int m = 0; m < 2; m++)
#pragma unroll
        for (int n = 0; n < 8; n++) {
            const int f = f0 + 16 * m + r0;
            const int t = t0 + 8 * n + c0;
            *(float2*)&dst[f * NT + t]       = make_float2(acc[m][n][0], acc[m][n][1]);
            *(float2*)&dst[(f + 8) * NT + t] = make_float2(acc[m][n][2], acc[m][n][3]);
        }
}

// ---------------------------------------------------------------------------
// Deterministic k-split reduction
// ---------------------------------------------------------------------------
__global__ void reduce_out(float* __restrict__ out) {
    int i = blockIdx.x * blockDim.x + threadIdx.x;
    const int n4 = BATCH * NF * NT / 4;
    if (i < n4) {
        const float4* p = (const float4*)g_part;
        float4 a = p[i];
#pragma unroll
        for (int k = 1; k < KS; k++) {
            float4 v = p[(size_t)k * n4 + i];
            a.x += v.x; a.y += v.y; a.z += v.z; a.w += v.w;
        }
        ((float4*)out)[i] = a;
    }
}

extern "C" void kernel_launch(void* const* d_in, const int* in_sizes, int n_in,
                              void* d_out, int out_size) {
    const float* sig = (const float*)d_in[0];
    float* out = (float*)d_out;

    prep_tables<<<(2 * LL * 128 + 255) / 256, 256>>>();

    cudaFuncSetAttribute(gabor_mma, cudaFuncAttributeMaxDynamicSharedMemorySize, SMEM_DYN);
    gabor_mma<<<dim3(KS, BATCH), 256, SMEM_DYN>>>(sig);

    reduce_out<<<(BATCH * NF * NT / 4 + 255) / 256, 256>>>(out);
}

// round 5
// speedup vs baseline: 2.0408x; 1.2077x over previous
#include <cuda_runtime.h>
#include <cuda_fp16.h>
#include <cstdint>

#define LL      8192
#define BATCH   32
#define NF      128
#define NT      128
#define KS      4
#define KR      (LL/KS)       // 2048
#define NSTG    (KR/64)       // 32 stages of k64

// ---- global tables / scratch ----
__device__ __align__(16) __half g_Chi[LL*NF];  // tiled [l/64][f][64k], fp16 hi
__device__ __align__(16) __half g_Clo[LL*NF];  // fp16 lo (C - Chi)
__device__ __align__(16) float  g_W[NT*LL];    // [t][l]
__device__ __align__(16) float  g_part[KS*BATCH*NF*NT];  // 8MB

// ---- smem layout (bytes). Rows padded to 144B => conflict-free ldsm ----
#define TILEB   18432                      // 128 rows * 144B
#define OFF_AH(buf) ((buf)*2*TILEB)
#define OFF_AL(buf) ((buf)*2*TILEB + TILEB)
#define OFF_B(buf)  (4*TILEB + (buf)*TILEB)
#define OFF_SIG     (6*TILEB)              // 110592
#define SMEM_DYN    (OFF_SIG + KR*4)       // 118784

// ---- PTX helpers ----
__device__ __forceinline__ uint32_t smem_u32(const void* p) {
    uint32_t a;
    asm("{ .reg .u64 t; cvta.to.shared.u64 t, %1; cvt.u32.u64 %0, t; }" : "=r"(a) : "l"(p));
    return a;
}
__device__ __forceinline__ void cpa16(uint32_t dst, const void* src) {
    asm volatile("cp.async.ca.shared.global [%0], [%1], 16;" :: "r"(dst), "l"(src));
}
#define CP_COMMIT() asm volatile("cp.async.commit_group;" ::: "memory")
#define CP_WAIT0()  asm volatile("cp.async.wait_group 0;" ::: "memory")

__device__ __forceinline__ void ldsm4(uint32_t r[4], uint32_t addr) {
    asm volatile("ldmatrix.sync.aligned.m8n8.x4.shared.b16 {%0,%1,%2,%3}, [%4];"
                 : "=r"(r[0]), "=r"(r[1]), "=r"(r[2]), "=r"(r[3]) : "r"(addr));
}
__device__ __forceinline__ void mma16816(float c[4], const uint32_t a[4],
                                         uint32_t b0, uint32_t b1) {
    asm volatile("mma.sync.aligned.m16n8k16.row.col.f32.f16.f16.f32 "
                 "{%0,%1,%2,%3}, {%4,%5,%6,%7}, {%8,%9}, {%0,%1,%2,%3};"
                 : "+f"(c[0]), "+f"(c[1]), "+f"(c[2]), "+f"(c[3])
                 : "r"(a[0]), "r"(a[1]), "r"(a[2]), "r"(a[3]), "r"(b0), "r"(b1));
}
// pack two fp32 -> f16x2 (first arg -> low half = lower k index)
__device__ __forceinline__ uint32_t pk2(float lo, float hi) {
    __half2 h = __floats2half2_rn(lo, hi);
    return *(uint32_t*)&h;
}

// ---------------------------------------------------------------------------
// Tables. Exact fp32-phase replication; fp16 hi/lo split of cos (22 bits eff).
// Layout: contiguous 16KB tiles [l/64][f][64k].
// ---------------------------------------------------------------------------
__global__ void prep_tables() {
    int idx = blockIdx.x * blockDim.x + threadIdx.x;
    const int totC = LL * NF;
    if (idx < totC) {
        int tile = idx >> 13;
        int r    = idx & 8191;
        int f    = r >> 6;
        int c    = r & 63;
        int l    = tile * 64 + c;
        int fi = (f * 4096) / 127;
        float fv = (float)fi, lf = (float)l;
        const float TP = 6.2831854820251465f;
        const float DD = 1.7484556e-7f;
        float a  = TP * fv;
        float e1 = fmaf(TP, fv, -a);
        float bb = a * lf;
        float e2 = fmaf(a, lf, -bb);
        float eps = (DD * (fv * lf) - e1 * lf - e2) * (1.0f / 8192.0f);
        int m = (fi * l) & (LL - 1);
        float x = (float)m * (1.0f / 4096.0f);
        float s, cc;
        sincospif(x, &s, &cc);
        float cosv = cc - eps * s;
        __half hi = __float2half_rn(cosv);
        float hif = __half2float(hi);
        g_Chi[idx] = hi;
        g_Clo[idx] = __float2half_rn(cosv - hif);
    } else if (idx < 2 * totC) {
        int j = idx - totC;
        int t = j >> 13;
        int l = j & 8191;
        int tci = (t * 8191) / 127;
        float diff = (float)l - (float)tci;
        float x = diff / 819.2f;
        g_W[j] = expf(-0.5f * (x * x));
    }
}

// ---------------------------------------------------------------------------
// Main GEMM: out_part[ks][b][f][t] = sum_k (Chi+Clo)[f,k] * fp16(sig[b,k]*W[t,k])
// 2-pass fp16 mma.sync m16n8k16. grid=(KS, BATCH), 256 threads.
// ---------------------------------------------------------------------------
__global__ void __launch_bounds__(256, 1)
gabor_mma(const float* __restrict__ sig) {
    extern __shared__ __align__(16) char smc[];
    const uint32_t smb = smem_u32(smc);
    const int tid = threadIdx.x, lane = tid & 31, wid = tid >> 5;
    const int ks = blockIdx.x, b = blockIdx.y;
    const int kbase = ks * KR;

    // signal chunk -> smem
    float* ssm = (float*)(smc + OFF_SIG);
    {
        const float4* sp = (const float4*)(sig + b * LL + kbase);
        float4* dp = (float4*)ssm;
        for (int i = tid; i < KR / 4; i += 256) dp[i] = sp[i];
    }
    __syncthreads();

    auto copyA = [&](int s, int buf) {
        const int gt = ks * NSTG + s;
        const char* srch = (const char*)g_Chi + (size_t)gt * 16384;
        const char* srcl = (const char*)g_Clo + (size_t)gt * 16384;
        const uint32_t dh = smb + OFF_AH(buf), dl = smb + OFF_AL(buf);
#pragma unroll
        for (int r = 0; r < 4; r++) {
            int j = tid + 256 * r;               // 0..1023 16B chunks
            uint32_t doff = (uint32_t)(j >> 3) * 144 + (j & 7) * 16;
            cpa16(dh + doff, srch + j * 16);
            cpa16(dl + doff, srcl + j * 16);
        }
    };

    const int tp = tid >> 1, hh = tid & 1;
    auto buildP = [&](int s, int buf) {
        const float* wrow = g_W + tp * LL + kbase + s * 64 + 32 * hh;
        const float* sp   = ssm + s * 64 + 32 * hh;
        char* ph = smc + OFF_B(buf) + tp * 144 + 64 * hh;
#pragma unroll
        for (int m = 0; m < 4; m++) {
            float4 wa = ((const float4*)wrow)[2 * m];
            float4 wb = ((const float4*)wrow)[2 * m + 1];
            float4 sa = ((const float4*)sp)[2 * m];
            float4 sb = ((const float4*)sp)[2 * m + 1];
            uint32_t h0 = pk2(sa.x * wa.x, sa.y * wa.y);
            uint32_t h1 = pk2(sa.z * wa.z, sa.w * wa.w);
            uint32_t h2 = pk2(sb.x * wb.x, sb.y * wb.y);
            uint32_t h3 = pk2(sb.z * wb.z, sb.w * wb.w);
            *(uint4*)(ph + 16 * m) = make_uint4(h0, h1, h2, h3);
        }
    };

    // prologue
    copyA(0, 0); CP_COMMIT();
    buildP(0, 0);

    float acc[2][8][4];
#pragma unroll
    for (int m = 0; m < 2; m++)
#pragma unroll
        for (int n = 0; n < 8; n++)
#pragma unroll
            for (int q = 0; q < 4; q++) acc[m][n][q] = 0.0f;

    const int f0 = (wid & 3) * 32, t0 = (wid >> 2) * 64;
    const uint32_t loff = (uint32_t)(lane & 15) * 144 + (lane >> 4) * 16;

    for (int s = 0; s < NSTG; s++) {
        CP_WAIT0();
        __syncthreads();
        const int buf = s & 1;
        if (s + 1 < NSTG) {
            copyA(s + 1, buf ^ 1); CP_COMMIT();
            buildP(s + 1, buf ^ 1);
        }
        const uint32_t aH = smb + OFF_AH(buf) + f0 * 144 + loff;
        const uint32_t aL = smb + OFF_AL(buf) + f0 * 144 + loff;
        const uint32_t bH = smb + OFF_B(buf)  + t0 * 144 + loff;
#pragma unroll
        for (int k16 = 0; k16 < 4; k16++) {
            const uint32_t kb = k16 * 32;
            uint32_t ah[2][4], al[2][4], bh[4][4];
            ldsm4(ah[0], aH + kb); ldsm4(ah[1], aH + 16 * 144 + kb);
            ldsm4(al[0], aL + kb); ldsm4(al[1], aL + 16 * 144 + kb);
#pragma unroll
            for (int j = 0; j < 4; j++)
                ldsm4(bh[j], bH + j * 16 * 144 + kb);
#pragma unroll
            for (int m = 0; m < 2; m++)
#pragma unroll
                for (int j = 0; j < 4; j++) {
                    mma16816(acc[m][2 * j],     ah[m], bh[j][0], bh[j][2]);
                    mma16816(acc[m][2 * j + 1], ah[m], bh[j][1], bh[j][3]);
                    mma16816(acc[m][2 * j],     al[m], bh[j][0], bh[j][2]);
                    mma16816(acc[m][2 * j + 1], al[m], bh[j][1], bh[j][3]);
                }
        }
    }

    // epilogue: write partials
    float* dst = g_part + (size_t)(ks * BATCH + b) * NF * NT;
    const int r0 = lane >> 2, c0 = (lane & 3) * 2;
#pragma unroll
    for (int m = 0; m < 2; m++)
#pragma unroll
        for (int n = 0; n < 8; n++) {
            const int f = f0 + 16 * m + r0;
            const int t = t0 + 8 * n + c0;
            *(float2*)&dst[f * NT + t]       = make_float2(acc[m][n][0], acc[m][n][1]);
            *(float2*)&dst[(f + 8) * NT + t] = make_float2(acc[m][n][2], acc[m][n][3]);
        }
}

// ---------------------------------------------------------------------------
// Deterministic k-split reduction
// ---------------------------------------------------------------------------
__global__ void reduce_out(float* __restrict__ out) {
    int i = blockIdx.x * blockDim.x + threadIdx.x;
    const int n4 = BATCH * NF * NT / 4;
    if (i < n4) {
        const float4* p = (const float4*)g_part;
        float4 a = p[i];
#pragma unroll
        for (int k = 1; k < KS; k++) {
            float4 v = p[(size_t)k * n4 + i];
            a.x += v.x; a.y += v.y; a.z += v.z; a.w += v.w;
        }
        ((float4*)out)[i] = a;
    }
}

extern "C" void kernel_launch(void* const* d_in, const int* in_sizes, int n_in,
                              void* d_out, int out_size) {
    const float* sig = (const float*)d_in[0];
    float* out = (float*)d_out;

    prep_tables<<<(2 * LL * 128 + 255) / 256, 256>>>();

    cudaFuncSetAttribute(gabor_mma, cudaFuncAttributeMaxDynamicSharedMemorySize, SMEM_DYN);
    gabor_mma<<<dim3(KS, BATCH), 256, SMEM_DYN>>>(sig);

    reduce_out<<<(BATCH * NF * NT / 4 + 255) / 256, 256>>>(out);
}

// round 6
// speedup vs baseline: 2.4842x; 1.2173x over previous
#include <cuda_runtime.h>
#include <cuda_fp16.h>
#include <cstdint>

#define LL      8192
#define BATCH   32
#define NF      128
#define NT      128
#define KS      4
#define KR      (LL/KS)       // 2048
#define NSTG    (KR/64)       // 32 stages of k64

// ---- global tables / scratch ----
__device__ __align__(16) __half g_C[LL*NF];   // tiled [l/64][f][64k], fp16
__device__ __align__(16) float  g_W[NT*LL];   // [t][l]
__device__ __align__(16) float  g_part[KS*BATCH*NF*NT];  // 8MB

// ---- smem layout (bytes). Rows padded to 144B => conflict-free ldsm ----
#define TILEB   18432                      // 128 rows * 144B
#define OFF_A(buf)  ((buf)*TILEB)
#define OFF_B(buf)  (2*TILEB + (buf)*TILEB)
#define OFF_SIG     (4*TILEB)              // 73728
#define SMEM_DYN    (OFF_SIG + KR*4)       // 81920

// ---- PTX helpers ----
__device__ __forceinline__ uint32_t smem_u32(const void* p) {
    uint32_t a;
    asm("{ .reg .u64 t; cvta.to.shared.u64 t, %1; cvt.u32.u64 %0, t; }" : "=r"(a) : "l"(p));
    return a;
}
__device__ __forceinline__ void cpa16(uint32_t dst, const void* src) {
    asm volatile("cp.async.ca.shared.global [%0], [%1], 16;" :: "r"(dst), "l"(src));
}
#define CP_COMMIT() asm volatile("cp.async.commit_group;" ::: "memory")
#define CP_WAIT0()  asm volatile("cp.async.wait_group 0;" ::: "memory")

__device__ __forceinline__ void ldsm4(uint32_t r[4], uint32_t addr) {
    asm volatile("ldmatrix.sync.aligned.m8n8.x4.shared.b16 {%0,%1,%2,%3}, [%4];"
                 : "=r"(r[0]), "=r"(r[1]), "=r"(r[2]), "=r"(r[3]) : "r"(addr));
}
__device__ __forceinline__ void mma16816(float c[4], const uint32_t a[4],
                                         uint32_t b0, uint32_t b1) {
    asm volatile("mma.sync.aligned.m16n8k16.row.col.f32.f16.f16.f32 "
                 "{%0,%1,%2,%3}, {%4,%5,%6,%7}, {%8,%9}, {%0,%1,%2,%3};"
                 : "+f"(c[0]), "+f"(c[1]), "+f"(c[2]), "+f"(c[3])
                 : "r"(a[0]), "r"(a[1]), "r"(a[2]), "r"(a[3]), "r"(b0), "r"(b1));
}
// pack two fp32 -> f16x2 (first arg -> low half = lower k index)
__device__ __forceinline__ uint32_t pk2(float lo, float hi) {
    __half2 h = __floats2half2_rn(lo, hi);
    return *(uint32_t*)&h;
}

// ---------------------------------------------------------------------------
// Tables. Exact fp32-phase replication; single fp16 C.
// Layout: contiguous 16KB tiles [l/64][f][64k].
// ---------------------------------------------------------------------------
__global__ void prep_tables() {
    int idx = blockIdx.x * blockDim.x + threadIdx.x;
    const int totC = LL * NF;
    if (idx < totC) {
        int tile = idx >> 13;
        int r    = idx & 8191;
        int f    = r >> 6;
        int c    = r & 63;
        int l    = tile * 64 + c;
        int fi = (f * 4096) / 127;
        float fv = (float)fi, lf = (float)l;
        const float TP = 6.2831854820251465f;
        const float DD = 1.7484556e-7f;
        float a  = TP * fv;
        float e1 = fmaf(TP, fv, -a);
        float bb = a * lf;
        float e2 = fmaf(a, lf, -bb);
        float eps = (DD * (fv * lf) - e1 * lf - e2) * (1.0f / 8192.0f);
        int m = (fi * l) & (LL - 1);
        float x = (float)m * (1.0f / 4096.0f);
        float s, cc;
        sincospif(x, &s, &cc);
        g_C[idx] = __float2half_rn(cc - eps * s);
    } else if (idx < 2 * totC) {
        int j = idx - totC;
        int t = j >> 13;
        int l = j & 8191;
        int tci = (t * 8191) / 127;
        float diff = (float)l - (float)tci;
        float x = diff / 819.2f;
        g_W[j] = expf(-0.5f * (x * x));
    }
}

// ---------------------------------------------------------------------------
// Main GEMM: out_part[ks][b][f][t] = sum_k C[f,k] * fp16(sig[b,k]*W[t,k])
// 1-pass fp16 mma.sync m16n8k16. grid=(KS, BATCH), 256 threads.
// ---------------------------------------------------------------------------
__global__ void __launch_bounds__(256, 1)
gabor_mma(const float* __restrict__ sig) {
    extern __shared__ __align__(16) char smc[];
    const uint32_t smb = smem_u32(smc);
    const int tid = threadIdx.x, lane = tid & 31, wid = tid >> 5;
    const int ks = blockIdx.x, b = blockIdx.y;
    const int kbase = ks * KR;

    // signal chunk -> smem
    float* ssm = (float*)(smc + OFF_SIG);
    {
        const float4* sp = (const float4*)(sig + b * LL + kbase);
        float4* dp = (float4*)ssm;
        for (int i = tid; i < KR / 4; i += 256) dp[i] = sp[i];
    }
    __syncthreads();

    auto copyA = [&](int s, int buf) {
        const int gt = ks * NSTG + s;
        const char* src = (const char*)g_C + (size_t)gt * 16384;
        const uint32_t dh = smb + OFF_A(buf);
#pragma unroll
        for (int r = 0; r < 4; r++) {
            int j = tid + 256 * r;               // 0..1023 16B chunks
            uint32_t doff = (uint32_t)(j >> 3) * 144 + (j & 7) * 16;
            cpa16(dh + doff, src + j * 16);
        }
    };

    const int tp = tid >> 1, hh = tid & 1;
    auto buildP = [&](int s, int buf) {
        const float* wrow = g_W + tp * LL + kbase + s * 64 + 32 * hh;
        const float* sp   = ssm + s * 64 + 32 * hh;
        char* ph = smc + OFF_B(buf) + tp * 144 + 64 * hh;
#pragma unroll
        for (int m = 0; m < 4; m++) {
            float4 wa = ((const float4*)wrow)[2 * m];
            float4 wb = ((const float4*)wrow)[2 * m + 1];
            float4 sa = ((const float4*)sp)[2 * m];
            float4 sb = ((const float4*)sp)[2 * m + 1];
            uint32_t h0 = pk2(sa.x * wa.x, sa.y * wa.y);
            uint32_t h1 = pk2(sa.z * wa.z, sa.w * wa.w);
            uint32_t h2 = pk2(sb.x * wb.x, sb.y * wb.y);
            uint32_t h3 = pk2(sb.z * wb.z, sb.w * wb.w);
            *(uint4*)(ph + 16 * m) = make_uint4(h0, h1, h2, h3);
        }
    };

    // prologue
    copyA(0, 0); CP_COMMIT();
    buildP(0, 0);

    float acc[2][8][4];
#pragma unroll
    for (int m = 0; m < 2; m++)
#pragma unroll
        for (int n = 0; n < 8; n++)
#pragma unroll
            for (int q = 0; q < 4; q++) acc[m][n][q] = 0.0f;

    const int f0 = (wid & 3) * 32, t0 = (wid >> 2) * 64;
    const uint32_t loff = (uint32_t)(lane & 15) * 144 + (lane >> 4) * 16;

    for (int s = 0; s < NSTG; s++) {
        CP_WAIT0();
        __syncthreads();
        const int buf = s & 1;
        if (s + 1 < NSTG) {
            copyA(s + 1, buf ^ 1); CP_COMMIT();
            buildP(s + 1, buf ^ 1);
        }
        const uint32_t aH = smb + OFF_A(buf) + f0 * 144 + loff;
        const uint32_t bH = smb + OFF_B(buf) + t0 * 144 + loff;
#pragma unroll
        for (int k16 = 0; k16 < 4; k16++) {
            const uint32_t kb = k16 * 32;
            uint32_t ah[2][4], bh[4][4];
            ldsm4(ah[0], aH + kb); ldsm4(ah[1], aH + 16 * 144 + kb);
#pragma unroll
            for (int j = 0; j < 4; j++)
                ldsm4(bh[j], bH + j * 16 * 144 + kb);
#pragma unroll
            for (int m = 0; m < 2; m++)
#pragma unroll
                for (int j = 0; j < 4; j++) {
                    mma16816(acc[m][2 * j],     ah[m], bh[j][0], bh[j][2]);
                    mma16816(acc[m][2 * j + 1], ah[m], bh[j][1], bh[j][3]);
                }
        }
    }

    // epilogue: write partials
    float* dst = g_part + (size_t)(ks * BATCH + b) * NF * NT;
    const int r0 = lane >> 2, c0 = (lane & 3) * 2;
#pragma unroll
    for (int m = 0; m < 2; m++)
#pragma unroll
        for (int n = 0; n < 8; n++) {
            const int f = f0 + 16 * m + r0;
            const int t = t0 + 8 * n + c0;
            *(float2*)&dst[f * NT + t]       = make_float2(acc[m][n][0], acc[m][n][1]);
            *(float2*)&dst[(f + 8) * NT + t] = make_float2(acc[m][n][2], acc[m][n][3]);
        }
}

// ---------------------------------------------------------------------------
// Deterministic k-split reduction
// ---------------------------------------------------------------------------
__global__ void reduce_out(float* __restrict__ out) {
    int i = blockIdx.x * blockDim.x + threadIdx.x;
    const int n4 = BATCH * NF * NT / 4;
    if (i < n4) {
        const float4* p = (const float4*)g_part;
        float4 a = p[i];
#pragma unroll
        for (int k = 1; k < KS; k++) {
            float4 v = p[(size_t)k * n4 + i];
            a.x += v.x; a.y += v.y; a.z += v.z; a.w += v.w;
        }
        ((float4*)out)[i] = a;
    }
}

extern "C" void kernel_launch(void* const* d_in, const int* in_sizes, int n_in,
                              void* d_out, int out_size) {
    const float* sig = (const float*)d_in[0];
    float* out = (float*)d_out;

    prep_tables<<<(2 * LL * 128 + 255) / 256, 256>>>();

    cudaFuncSetAttribute(gabor_mma, cudaFuncAttributeMaxDynamicSharedMemorySize, SMEM_DYN);
    gabor_mma<<<dim3(KS, BATCH), 256, SMEM_DYN>>>(sig);

    reduce_out<<<(BATCH * NF * NT / 4 + 255) / 256, 256>>>(out);
}

// round 7
// speedup vs baseline: 4.0453x; 1.6284x over previous
#include <cuda_runtime.h>
#include <cuda_fp16.h>
#include <cstdint>

#define LL      8192
#define BATCH   32
#define NF      128
#define NT      128
#define KS      4
#define KR      (LL/KS)       // 2048
#define NSTG    (KR/64)       // 32 stages of k64
#define NTH     512

// ---- global tables / scratch ----
__device__ __align__(16) __half g_C[LL*NF];   // tiled [l/64][f][64k], fp16
__device__ __align__(16) __half g_Wh[NT*LL];  // [t][l] fp16
__device__ __align__(16) float  g_part[KS*BATCH*NF*NT];  // 8MB

// ---- smem layout (bytes). Rows padded to 144B => conflict-free ldsm ----
#define TILEB    18432                     // 128 rows * 144B
#define OFF_A(buf)  ((buf)*TILEB)
#define OFF_B(buf)  (2*TILEB + (buf)*TILEB)
#define OFF_SIGH    (4*TILEB)              // 73728, 2048 halfs = 4096B
#define SMEM_DYN    (OFF_SIGH + KR*2 + 128)

// ---- PTX helpers ----
__device__ __forceinline__ uint32_t smem_u32(const void* p) {
    uint32_t a;
    asm("{ .reg .u64 t; cvta.to.shared.u64 t, %1; cvt.u32.u64 %0, t; }" : "=r"(a) : "l"(p));
    return a;
}
__device__ __forceinline__ void cpa16(uint32_t dst, const void* src) {
    asm volatile("cp.async.ca.shared.global [%0], [%1], 16;" :: "r"(dst), "l"(src));
}
#define CP_COMMIT() asm volatile("cp.async.commit_group;" ::: "memory")
#define CP_WAIT0()  asm volatile("cp.async.wait_group 0;" ::: "memory")

__device__ __forceinline__ void ldsm4(uint32_t r[4], uint32_t addr) {
    asm volatile("ldmatrix.sync.aligned.m8n8.x4.shared.b16 {%0,%1,%2,%3}, [%4];"
                 : "=r"(r[0]), "=r"(r[1]), "=r"(r[2]), "=r"(r[3]) : "r"(addr));
}
__device__ __forceinline__ void mma16816(float c[4], const uint32_t a[4],
                                         uint32_t b0, uint32_t b1) {
    asm volatile("mma.sync.aligned.m16n8k16.row.col.f32.f16.f16.f32 "
                 "{%0,%1,%2,%3}, {%4,%5,%6,%7}, {%8,%9}, {%0,%1,%2,%3};"
                 : "+f"(c[0]), "+f"(c[1]), "+f"(c[2]), "+f"(c[3])
                 : "r"(a[0]), "r"(a[1]), "r"(a[2]), "r"(a[3]), "r"(b0), "r"(b1));
}
__device__ __forceinline__ uint32_t hm2(uint32_t a, uint32_t b) {
    __half2 r = __hmul2(*(__half2*)&a, *(__half2*)&b);
    return *(uint32_t*)&r;
}

// ---------------------------------------------------------------------------
// Tables. Exact fp32-phase replication; fp16 C (tiled) and fp16 W ([t][l]).
// ---------------------------------------------------------------------------
__global__ void prep_tables() {
    int idx = blockIdx.x * blockDim.x + threadIdx.x;
    const int totC = LL * NF;
    if (idx < totC) {
        int tile = idx >> 13;
        int r    = idx & 8191;
        int f    = r >> 6;
        int c    = r & 63;
        int l    = tile * 64 + c;
        int fi = (f * 4096) / 127;
        float fv = (float)fi, lf = (float)l;
        const float TP = 6.2831854820251465f;
        const float DD = 1.7484556e-7f;
        float a  = TP * fv;
        float e1 = fmaf(TP, fv, -a);
        float bb = a * lf;
        float e2 = fmaf(a, lf, -bb);
        float eps = (DD * (fv * lf) - e1 * lf - e2) * (1.0f / 8192.0f);
        int m = (fi * l) & (LL - 1);
        float x = (float)m * (1.0f / 4096.0f);
        float s, cc;
        sincospif(x, &s, &cc);
        g_C[idx] = __float2half_rn(cc - eps * s);
    } else if (idx < 2 * totC) {
        int j = idx - totC;
        int t = j >> 13;
        int l = j & 8191;
        int tci = (t * 8191) / 127;
        float diff = (float)l - (float)tci;
        float x = diff / 819.2f;
        g_Wh[j] = __float2half_rn(expf(-0.5f * (x * x)));
    }
}

// ---------------------------------------------------------------------------
// Main GEMM: out_part[ks][b][f][t] = sum_k C[f,k] * fp16(sig[b,k])*fp16(W[t,k])
// fp16 mma.sync m16n8k16. grid=(KS, BATCH), 512 threads, warp tile 32x32.
// ---------------------------------------------------------------------------
__global__ void __launch_bounds__(NTH, 1)
gabor_mma(const float* __restrict__ sig) {
    extern __shared__ __align__(16) char smc[];
    const uint32_t smb = smem_u32(smc);
    const int tid = threadIdx.x, lane = tid & 31, wid = tid >> 5;
    const int ks = blockIdx.x, b = blockIdx.y;
    const int kbase = ks * KR;

    // signal chunk -> smem as half2
    {
        const float4* sp = (const float4*)(sig + b * LL + kbase);
        uint2* dp = (uint2*)(smc + OFF_SIGH);
        for (int i = tid; i < KR / 4; i += NTH) {
            float4 v = sp[i];
            __half2 a = __floats2half2_rn(v.x, v.y);
            __half2 c = __floats2half2_rn(v.z, v.w);
            dp[i] = make_uint2(*(uint32_t*)&a, *(uint32_t*)&c);
        }
    }
    __syncthreads();

    auto copyA = [&](int s, int buf) {
        const int gt = ks * NSTG + s;
        const char* src = (const char*)g_C + (size_t)gt * 16384;
        const uint32_t dh = smb + OFF_A(buf);
#pragma unroll
        for (int r = 0; r < 2; r++) {
            int j = tid + NTH * r;               // 0..1023 16B chunks
            uint32_t doff = (uint32_t)(j >> 3) * 144 + (j & 7) * 16;
            cpa16(dh + doff, src + j * 16);
        }
    };

    const int tp = tid >> 2, qq = tid & 3;       // row t, quarter
    auto buildP = [&](int s, int buf) {
        const uint4* wp = (const uint4*)(g_Wh + (size_t)tp * LL + kbase + s * 64 + qq * 16);
        uint4 w0 = wp[0], w1 = wp[1];
        const uint4* sp = (const uint4*)(smc + OFF_SIGH + (s * 64 + qq * 16) * 2);
        uint4 s0 = sp[0], s1 = sp[1];
        uint4 p0, p1;
        p0.x = hm2(w0.x, s0.x); p0.y = hm2(w0.y, s0.y);
        p0.z = hm2(w0.z, s0.z); p0.w = hm2(w0.w, s0.w);
        p1.x = hm2(w1.x, s1.x); p1.y = hm2(w1.y, s1.y);
        p1.z = hm2(w1.z, s1.z); p1.w = hm2(w1.w, s1.w);
        char* ph = smc + OFF_B(buf) + tp * 144 + qq * 32;
        *(uint4*)ph = p0;
        *(uint4*)(ph + 16) = p1;
    };

    // prologue
    copyA(0, 0); CP_COMMIT();
    buildP(0, 0);

    float acc[2][4][4];
#pragma unroll
    for (int m = 0; m < 2; m++)
#pragma unroll
        for (int n = 0; n < 4; n++)
#pragma unroll
            for (int q = 0; q < 4; q++) acc[m][n][q] = 0.0f;

    const int f0 = (wid & 3) * 32, t0 = (wid >> 2) * 32;
    const uint32_t loff = (uint32_t)(lane & 15) * 144 + (lane >> 4) * 16;

    for (int s = 0; s < NSTG; s++) {
        CP_WAIT0();
        __syncthreads();
        const int buf = s & 1;
        if (s + 1 < NSTG) {
            copyA(s + 1, buf ^ 1); CP_COMMIT();
            buildP(s + 1, buf ^ 1);
        }
        const uint32_t aH = smb + OFF_A(buf) + f0 * 144 + loff;
        const uint32_t bH = smb + OFF_B(buf) + t0 * 144 + loff;
#pragma unroll
        for (int k16 = 0; k16 < 4; k16++) {
            const uint32_t kb = k16 * 32;
            uint32_t ah[2][4], bh[2][4];
            ldsm4(ah[0], aH + kb); ldsm4(ah[1], aH + 16 * 144 + kb);
            ldsm4(bh[0], bH + kb); ldsm4(bh[1], bH + 16 * 144 + kb);
#pragma unroll
            for (int m = 0; m < 2; m++)
#pragma unroll
                for (int j = 0; j < 2; j++) {
                    mma16816(acc[m][2 * j],     ah[m], bh[j][0], bh[j][2]);
                    mma16816(acc[m][2 * j + 1], ah[m], bh[j][1], bh[j][3]);
                }
        }
    }

    // epilogue: write partials
    float* dst = g_part + (size_t)(ks * BATCH + b) * NF * NT;
    const int r0 = lane >> 2, c0 = (lane & 3) * 2;
#pragma unroll
    for (int m = 0; m < 2; m++)
#pragma unroll
        for (int n = 0; n < 4; n++) {
            const int f = f0 + 16 * m + r0;
            const int t = t0 + 16 * (n >> 1) + 8 * (n & 1) + c0;
            *(float2*)&dst[f * NT + t]       = make_float2(acc[m][n][0], acc[m][n][1]);
            *(float2*)&dst[(f + 8) * NT + t] = make_float2(acc[m][n][2], acc[m][n][3]);
        }
}

// ---------------------------------------------------------------------------
// Deterministic k-split reduction
// ---------------------------------------------------------------------------
__global__ void reduce_out(float* __restrict__ out) {
    int i = blockIdx.x * blockDim.x + threadIdx.x;
    const int n4 = BATCH * NF * NT / 4;
    if (i < n4) {
        const float4* p = (const float4*)g_part;
        float4 a = p[i];
#pragma unroll
        for (int k = 1; k < KS; k++) {
            float4 v = p[(size_t)k * n4 + i];
            a.x += v.x; a.y += v.y; a.z += v.z; a.w += v.w;
        }
        ((float4*)out)[i] = a;
    }
}

extern "C" void kernel_launch(void* const* d_in, const int* in_sizes, int n_in,
                              void* d_out, int out_size) {
    const float* sig = (const float*)d_in[0];
    float* out = (float*)d_out;

    prep_tables<<<(2 * LL * 128 + 255) / 256, 256>>>();

    cudaFuncSetAttribute(gabor_mma, cudaFuncAttributeMaxDynamicSharedMemorySize, SMEM_DYN);
    gabor_mma<<<dim3(KS, BATCH), NTH, SMEM_DYN>>>(sig);

    reduce_out<<<(BATCH * NF * NT / 4 + 255) / 256, 256>>>(out);
}